// round 3
// baseline (speedup 1.0000x reference)
#include <cuda_runtime.h>
#include <cstdint>

// Problem constants (fixed shapes from reference)
#define NB   16          // batch
#define C    256         // channels
#define CH   128         // C/2 hidden / selected count
#define HW   16384       // 128*128 spatial
#define HW4  4096        // HW / 4 (float4)

// Scratch (allocation-free: __device__ globals)
__device__ float g_z[NB * C];     // per (n,c) channel means
__device__ int   g_src[NB * C];   // g_src[n*C + rank] = source channel

// ---------------------------------------------------------------------------
// Kernel 1: channel means. One block per (n,c). 256 threads, float4 loads.
// ---------------------------------------------------------------------------
__global__ __launch_bounds__(256) void mean_kernel(const float* __restrict__ x)
{
    const int nc = blockIdx.x;                       // 0 .. NB*C-1
    const float4* __restrict__ p =
        reinterpret_cast<const float4*>(x + (size_t)nc * HW);

    float s = 0.0f;
    #pragma unroll
    for (int k = 0; k < HW4 / 256; ++k) {
        float4 v = p[threadIdx.x + k * 256];
        s += (v.x + v.y) + (v.z + v.w);
    }

    // warp reduce then cross-warp via shared
    #pragma unroll
    for (int o = 16; o > 0; o >>= 1)
        s += __shfl_xor_sync(0xFFFFFFFFu, s, o);

    __shared__ float red[8];
    const int lane = threadIdx.x & 31, wid = threadIdx.x >> 5;
    if (lane == 0) red[wid] = s;
    __syncthreads();
    if (threadIdx.x == 0) {
        float t = 0.0f;
        #pragma unroll
        for (int w = 0; w < 8; ++w) t += red[w];
        g_z[nc] = t * (1.0f / (float)HW);
    }
}

// ---------------------------------------------------------------------------
// Kernel 2: MLP + sigmoid + stable descending rank. One block per batch n.
// 256 threads. Tiny — latency bound.
// ---------------------------------------------------------------------------
__global__ __launch_bounds__(256) void mlp_rank_kernel(
    const float* __restrict__ W1, const float* __restrict__ b1,
    const float* __restrict__ W2, const float* __restrict__ b2)
{
    const int n = blockIdx.x;
    const int t = threadIdx.x;

    __shared__ float z[C];
    __shared__ float h[CH];
    __shared__ float sc[C];

    z[t] = g_z[n * C + t];
    __syncthreads();

    // h = relu(z @ W1.T + b1)   (W1 is [CH, C] row-major)
    if (t < CH) {
        const float* __restrict__ w = W1 + t * C;
        float a = b1[t];
        #pragma unroll 8
        for (int k = 0; k < C; ++k) a = fmaf(z[k], w[k], a);
        h[t] = a > 0.0f ? a : 0.0f;
    }
    __syncthreads();

    // scores = sigmoid(h @ W2.T + b2)   (W2 is [C, CH] row-major)
    {
        const float* __restrict__ w = W2 + t * CH;
        float a = b2[t];
        #pragma unroll 8
        for (int k = 0; k < CH; ++k) a = fmaf(h[k], w[k], a);
        sc[t] = 1.0f / (1.0f + expf(-a));
    }
    __syncthreads();

    // Stable descending rank, matching jnp.argsort(-scores):
    // rank = #{j : s[j] > s[t]}  +  #{j < t : s[j] == s[t]}
    const float mys = sc[t];
    int rank = 0;
    #pragma unroll 8
    for (int j = 0; j < C; ++j) {
        float sj = sc[j];
        rank += (sj > mys) || (sj == mys && j < t);
    }
    g_src[n * C + rank] = t;   // output slot 'rank' reads channel 't'
}

// ---------------------------------------------------------------------------
// Kernel 3: permuted channel gather. grid = (NB*C, 4); each block copies a
// 4096-float (16 KB) slice of one channel with float4.
// Output layout: [selected (NB,CH,H,W)] then [remaining (NB,CH,H,W)].
// ---------------------------------------------------------------------------
__global__ __launch_bounds__(256) void gather_kernel(
    const float* __restrict__ x, float* __restrict__ out)
{
    const int b    = blockIdx.x;        // 0 .. NB*C-1  -> (n, slot)
    const int n    = b >> 8;
    const int slot = b & 255;
    const int c    = g_src[b];

    const float4* __restrict__ src =
        reinterpret_cast<const float4*>(x + ((size_t)(n * C + c)) * HW);

    size_t dst_ch;
    if (slot < CH) dst_ch = (size_t)n * CH + slot;                       // selected
    else           dst_ch = (size_t)NB * CH + (size_t)n * CH + (slot - CH); // remaining
    float4* __restrict__ dst = reinterpret_cast<float4*>(out + dst_ch * HW);

    const int base = blockIdx.y * (HW4 / 4);   // 1024 float4 per y-slice
    #pragma unroll
    for (int k = 0; k < 4; ++k) {
        const int i = base + threadIdx.x + k * 256;
        dst[i] = src[i];
    }
}

// ---------------------------------------------------------------------------
extern "C" void kernel_launch(void* const* d_in, const int* in_sizes, int n_in,
                              void* d_out, int out_size)
{
    const float* x  = (const float*)d_in[0];
    const float* W1 = (const float*)d_in[1];
    const float* b1 = (const float*)d_in[2];
    const float* W2 = (const float*)d_in[3];
    const float* b2 = (const float*)d_in[4];
    float* out = (float*)d_out;

    mean_kernel<<<NB * C, 256>>>(x);
    mlp_rank_kernel<<<NB, 256>>>(W1, b1, W2, b2);
    gather_kernel<<<dim3(NB * C, 4), 256>>>(x, out);
}

// round 4
// speedup vs baseline: 1.0226x; 1.0226x over previous
#include <cuda_runtime.h>
#include <cstdint>

// Problem constants (fixed shapes from reference)
#define NB   16          // batch
#define C    256         // channels
#define CH   128         // C/2 hidden / selected count
#define HW   16384       // 128*128 spatial
#define HW4  4096        // HW / 4 (float4)

// Scratch (allocation-free: __device__ globals)
__device__ float g_z[NB * C];     // per (n,c) channel means
__device__ int   g_src[NB * C];   // g_src[n*C + rank] = source channel

// ---------------------------------------------------------------------------
// Kernel 1: channel means. One block per (n,c). 256 threads, float4 loads.
// Streaming loads (__ldcs): x is re-read by gather but 256MB >> L2 anyway.
// ---------------------------------------------------------------------------
__global__ __launch_bounds__(256) void mean_kernel(const float* __restrict__ x)
{
    const int nc = blockIdx.x;                       // 0 .. NB*C-1
    const float4* __restrict__ p =
        reinterpret_cast<const float4*>(x + (size_t)nc * HW);

    float s = 0.0f;
    #pragma unroll
    for (int k = 0; k < HW4 / 256; ++k) {
        float4 v = __ldcs(&p[threadIdx.x + k * 256]);
        s += (v.x + v.y) + (v.z + v.w);
    }

    // warp reduce then cross-warp via shared
    #pragma unroll
    for (int o = 16; o > 0; o >>= 1)
        s += __shfl_xor_sync(0xFFFFFFFFu, s, o);

    __shared__ float red[8];
    const int lane = threadIdx.x & 31, wid = threadIdx.x >> 5;
    if (lane == 0) red[wid] = s;
    __syncthreads();
    if (threadIdx.x == 0) {
        float t = 0.0f;
        #pragma unroll
        for (int w = 0; w < 8; ++w) t += red[w];
        g_z[nc] = t * (1.0f / (float)HW);
    }
}

// ---------------------------------------------------------------------------
// Kernel 2: MLP + sigmoid + stable descending rank. One block per batch n.
// ---------------------------------------------------------------------------
__global__ __launch_bounds__(256) void mlp_rank_kernel(
    const float* __restrict__ W1, const float* __restrict__ b1,
    const float* __restrict__ W2, const float* __restrict__ b2)
{
    const int n = blockIdx.x;
    const int t = threadIdx.x;

    __shared__ float z[C];
    __shared__ float h[CH];
    __shared__ float sc[C];

    z[t] = g_z[n * C + t];
    __syncthreads();

    // h = relu(z @ W1.T + b1)   (W1 is [CH, C] row-major)
    if (t < CH) {
        const float* __restrict__ w = W1 + t * C;
        float a = b1[t];
        #pragma unroll 8
        for (int k = 0; k < C; ++k) a = fmaf(z[k], w[k], a);
        h[t] = a > 0.0f ? a : 0.0f;
    }
    __syncthreads();

    // scores = sigmoid(h @ W2.T + b2)   (W2 is [C, CH] row-major)
    {
        const float* __restrict__ w = W2 + t * CH;
        float a = b2[t];
        #pragma unroll 8
        for (int k = 0; k < CH; ++k) a = fmaf(h[k], w[k], a);
        sc[t] = 1.0f / (1.0f + expf(-a));
    }
    __syncthreads();

    // Stable descending rank, matching jnp.argsort(-scores):
    // rank = #{j : s[j] > s[t]}  +  #{j < t : s[j] == s[t]}
    const float mys = sc[t];
    int rank = 0;
    #pragma unroll 8
    for (int j = 0; j < C; ++j) {
        float sj = sc[j];
        rank += (sj > mys) || (sj == mys && j < t);
    }
    g_src[n * C + rank] = t;   // output slot 'rank' reads channel 't'
}

// ---------------------------------------------------------------------------
// Kernel 3: permuted channel gather. grid = (NB*C, 2); each block copies a
// 32KB half-channel. Loads are front-batched 8-deep (MLP_p1=8) into regs,
// then stored — decouples the read and write streams and hides DRAM latency.
// Output layout: [selected (NB,CH,H,W)] then [remaining (NB,CH,H,W)].
// ---------------------------------------------------------------------------
__global__ __launch_bounds__(256) void gather_kernel(
    const float* __restrict__ x, float* __restrict__ out)
{
    const int b    = blockIdx.x;        // 0 .. NB*C-1  -> (n, slot)
    const int n    = b >> 8;
    const int slot = b & 255;
    const int c    = __ldg(&g_src[b]);

    const float4* __restrict__ src =
        reinterpret_cast<const float4*>(x + ((size_t)(n * C + c)) * HW);

    size_t dst_ch;
    if (slot < CH) dst_ch = (size_t)n * CH + slot;                          // selected
    else           dst_ch = (size_t)NB * CH + (size_t)n * CH + (slot - CH); // remaining
    float4* __restrict__ dst = reinterpret_cast<float4*>(out + dst_ch * HW);

    // half-channel: 2048 float4 per y-slice; 8 float4 per thread, batched
    const int base = blockIdx.y * (HW4 / 2) + threadIdx.x;

    float4 r[8];
    #pragma unroll
    for (int k = 0; k < 8; ++k)
        r[k] = __ldcs(&src[base + k * 256]);
    #pragma unroll
    for (int k = 0; k < 8; ++k)
        __stcs(&dst[base + k * 256], r[k]);
}

// ---------------------------------------------------------------------------
extern "C" void kernel_launch(void* const* d_in, const int* in_sizes, int n_in,
                              void* d_out, int out_size)
{
    const float* x  = (const float*)d_in[0];
    const float* W1 = (const float*)d_in[1];
    const float* b1 = (const float*)d_in[2];
    const float* W2 = (const float*)d_in[3];
    const float* b2 = (const float*)d_in[4];
    float* out = (float*)d_out;

    mean_kernel<<<NB * C, 256>>>(x);
    mlp_rank_kernel<<<NB, 256>>>(W1, b1, W2, b2);
    gather_kernel<<<dim3(NB * C, 2), 256>>>(x, out);
}

// round 5
// speedup vs baseline: 1.0241x; 1.0016x over previous
#include <cuda_runtime.h>
#include <cstdint>

// Problem constants (fixed shapes from reference)
#define NB   16          // batch
#define C    256         // channels
#define CH   128         // C/2 hidden / selected count
#define HW   16384       // 128*128 spatial
#define HW4  4096        // HW / 4 (float4)

// Scratch (allocation-free: __device__ globals)
__device__ float g_z[NB * C];     // per (n,c) channel means
__device__ int   g_dst[NB * C];   // g_dst[n*C + c] = output rank/slot of channel c

// ---------------------------------------------------------------------------
// Kernel 1: channel means. One block per (n,c). 256 threads, float4 loads.
// ---------------------------------------------------------------------------
__global__ __launch_bounds__(256) void mean_kernel(const float* __restrict__ x)
{
    const int nc = blockIdx.x;                       // 0 .. NB*C-1
    const float4* __restrict__ p =
        reinterpret_cast<const float4*>(x + (size_t)nc * HW);

    float s = 0.0f;
    #pragma unroll
    for (int k = 0; k < HW4 / 256; ++k) {
        float4 v = __ldcs(&p[threadIdx.x + k * 256]);
        s += (v.x + v.y) + (v.z + v.w);
    }

    // warp reduce then cross-warp via shared
    #pragma unroll
    for (int o = 16; o > 0; o >>= 1)
        s += __shfl_xor_sync(0xFFFFFFFFu, s, o);

    __shared__ float red[8];
    const int lane = threadIdx.x & 31, wid = threadIdx.x >> 5;
    if (lane == 0) red[wid] = s;
    __syncthreads();
    if (threadIdx.x == 0) {
        float t = 0.0f;
        #pragma unroll
        for (int w = 0; w < 8; ++w) t += red[w];
        g_z[nc] = t * (1.0f / (float)HW);
    }
}

// ---------------------------------------------------------------------------
// Kernel 2: MLP + sigmoid + stable descending rank. One block per batch n.
// Emits the FORWARD map: channel c -> output slot (inverse of argsort order).
// ---------------------------------------------------------------------------
__global__ __launch_bounds__(256) void mlp_rank_kernel(
    const float* __restrict__ W1, const float* __restrict__ b1,
    const float* __restrict__ W2, const float* __restrict__ b2)
{
    const int n = blockIdx.x;
    const int t = threadIdx.x;

    __shared__ float z[C];
    __shared__ float h[CH];
    __shared__ float sc[C];

    z[t] = g_z[n * C + t];
    __syncthreads();

    // h = relu(z @ W1.T + b1)   (W1 is [CH, C] row-major)
    if (t < CH) {
        const float* __restrict__ w = W1 + t * C;
        float a = b1[t];
        #pragma unroll 8
        for (int k = 0; k < C; ++k) a = fmaf(z[k], w[k], a);
        h[t] = a > 0.0f ? a : 0.0f;
    }
    __syncthreads();

    // scores = sigmoid(h @ W2.T + b2)   (W2 is [C, CH] row-major)
    {
        const float* __restrict__ w = W2 + t * CH;
        float a = b2[t];
        #pragma unroll 8
        for (int k = 0; k < CH; ++k) a = fmaf(h[k], w[k], a);
        sc[t] = 1.0f / (1.0f + expf(-a));
    }
    __syncthreads();

    // Stable descending rank, matching jnp.argsort(-scores):
    // rank = #{j : s[j] > s[t]}  +  #{j < t : s[j] == s[t]}
    const float mys = sc[t];
    int rank = 0;
    #pragma unroll 8
    for (int j = 0; j < C; ++j) {
        float sj = sc[j];
        rank += (sj > mys) || (sj == mys && j < t);
    }
    g_dst[n * C + t] = rank;   // channel t lands in output slot 'rank'
}

// ---------------------------------------------------------------------------
// Kernel 3: SCATTER copy. Block b = (n, c) reads channel c LINEARLY (same
// DRAM-friendly order as mean_kernel, proven 6.5 TB/s) and writes it to its
// permuted output slot. Writes are reordered/absorbed by L2.
// 16 float4 per thread in two 8-deep batches (64 KB per block, grid=4096).
// Output layout: [selected (NB,CH,H,W)] then [remaining (NB,CH,H,W)].
// ---------------------------------------------------------------------------
__global__ __launch_bounds__(256) void scatter_kernel(
    const float* __restrict__ x, float* __restrict__ out)
{
    const int b    = blockIdx.x;        // 0 .. NB*C-1  -> (n, c)
    const int n    = b >> 8;
    const int slot = __ldg(&g_dst[b]);

    const float4* __restrict__ src =
        reinterpret_cast<const float4*>(x + (size_t)b * HW);   // linear read!

    size_t dst_ch;
    if (slot < CH) dst_ch = (size_t)n * CH + slot;                          // selected
    else           dst_ch = (size_t)NB * CH + (size_t)n * CH + (slot - CH); // remaining
    float4* __restrict__ dst = reinterpret_cast<float4*>(out + dst_ch * HW);

    #pragma unroll
    for (int half = 0; half < 2; ++half) {
        const int base = half * (HW4 / 2) + threadIdx.x;
        float4 r[8];
        #pragma unroll
        for (int k = 0; k < 8; ++k)
            r[k] = __ldcs(&src[base + k * 256]);
        #pragma unroll
        for (int k = 0; k < 8; ++k)
            __stcs(&dst[base + k * 256], r[k]);
    }
}

// ---------------------------------------------------------------------------
extern "C" void kernel_launch(void* const* d_in, const int* in_sizes, int n_in,
                              void* d_out, int out_size)
{
    const float* x  = (const float*)d_in[0];
    const float* W1 = (const float*)d_in[1];
    const float* b1 = (const float*)d_in[2];
    const float* W2 = (const float*)d_in[3];
    const float* b2 = (const float*)d_in[4];
    float* out = (float*)d_out;

    mean_kernel<<<NB * C, 256>>>(x);
    mlp_rank_kernel<<<NB, 256>>>(W1, b1, W2, b2);
    scatter_kernel<<<NB * C, 256>>>(x, out);
}

// round 6
// speedup vs baseline: 1.1538x; 1.1266x over previous
#include <cuda_runtime.h>
#include <cstdint>

#define NB   16          // batch
#define C    256         // channels
#define CH   128         // C/2 hidden / selected count
#define HW   16384       // 128*128 spatial
#define HW4  4096        // HW / 4 (float4)

__device__ float g_z[NB * C];     // per (n,c) channel means
__device__ int   g_dst[NB * C];   // g_dst[n*C + c] = output slot of channel c

// ---------------------------------------------------------------------------
// Kernel 1: channel means. One block per (n,c). Default caching so the TAIL
// of x stays resident in L2 for the scatter kernel (L2 persists across
// launches; only L1 is flushed).
// ---------------------------------------------------------------------------
__global__ __launch_bounds__(256) void mean_kernel(const float* __restrict__ x)
{
    const int nc = blockIdx.x;
    const float4* __restrict__ p =
        reinterpret_cast<const float4*>(x + (size_t)nc * HW);

    float s = 0.0f;
    #pragma unroll
    for (int k = 0; k < HW4 / 256; ++k) {
        float4 v = p[threadIdx.x + k * 256];
        s += (v.x + v.y) + (v.z + v.w);
    }

    #pragma unroll
    for (int o = 16; o > 0; o >>= 1)
        s += __shfl_xor_sync(0xFFFFFFFFu, s, o);

    __shared__ float red[8];
    const int lane = threadIdx.x & 31, wid = threadIdx.x >> 5;
    if (lane == 0) red[wid] = s;
    __syncthreads();
    if (threadIdx.x == 0) {
        float t = 0.0f;
        #pragma unroll
        for (int w = 0; w < 8; ++w) t += red[w];
        g_z[nc] = t * (1.0f / (float)HW);
    }
}

// ---------------------------------------------------------------------------
// Kernel 2: MLP + sigmoid + stable rank. One block per batch n, 256 threads.
// Warp-per-output GEMVs with coalesced float4 weight loads + shfl reduce.
// ---------------------------------------------------------------------------
__global__ __launch_bounds__(256) void mlp_rank_kernel(
    const float* __restrict__ W1, const float* __restrict__ b1,
    const float* __restrict__ W2, const float* __restrict__ b2)
{
    const int n    = blockIdx.x;
    const int t    = threadIdx.x;
    const int lane = t & 31;
    const int wid  = t >> 5;          // 8 warps

    __shared__ __align__(16) float z[C];
    __shared__ __align__(16) float h[CH];
    __shared__ float sc[C];

    z[t] = g_z[n * C + t];
    __syncthreads();

    const float4* __restrict__ z4 = reinterpret_cast<const float4*>(z);

    // h = relu(z @ W1.T + b1): warp 'wid' computes outputs wid*16 .. wid*16+15
    #pragma unroll
    for (int ii = 0; ii < 16; ++ii) {
        const int i = wid * 16 + ii;
        const float4* __restrict__ w4 =
            reinterpret_cast<const float4*>(W1 + i * C);       // 64 float4
        float4 wa = w4[lane], wb = w4[lane + 32];
        float4 za = z4[lane], zb = z4[lane + 32];
        float s = wa.x * za.x;
        s = fmaf(wa.y, za.y, s); s = fmaf(wa.z, za.z, s); s = fmaf(wa.w, za.w, s);
        s = fmaf(wb.x, zb.x, s); s = fmaf(wb.y, zb.y, s);
        s = fmaf(wb.z, zb.z, s); s = fmaf(wb.w, zb.w, s);
        #pragma unroll
        for (int o = 16; o > 0; o >>= 1)
            s += __shfl_xor_sync(0xFFFFFFFFu, s, o);
        if (lane == 0) {
            float a = s + b1[i];
            h[i] = a > 0.0f ? a : 0.0f;
        }
    }
    __syncthreads();

    const float4* __restrict__ h4 = reinterpret_cast<const float4*>(h);

    // scores = sigmoid(h @ W2.T + b2): warp 'wid' computes outputs wid*32 ..
    #pragma unroll
    for (int ii = 0; ii < 32; ++ii) {
        const int i = wid * 32 + ii;
        const float4* __restrict__ w4 =
            reinterpret_cast<const float4*>(W2 + i * CH);      // 32 float4
        float4 wa = w4[lane];
        float4 ha = h4[lane];
        float s = wa.x * ha.x;
        s = fmaf(wa.y, ha.y, s); s = fmaf(wa.z, ha.z, s); s = fmaf(wa.w, ha.w, s);
        #pragma unroll
        for (int o = 16; o > 0; o >>= 1)
            s += __shfl_xor_sync(0xFFFFFFFFu, s, o);
        if (lane == 0)
            sc[i] = 1.0f / (1.0f + expf(-(s + b2[i])));
    }
    __syncthreads();

    // Stable descending rank (matches jnp.argsort(-scores)):
    const float mys = sc[t];
    int rank = 0;
    #pragma unroll 8
    for (int j = 0; j < C; ++j) {
        float sj = sc[j];
        rank += (sj > mys) || (sj == mys && j < t);
    }
    g_dst[n * C + t] = rank;
}

// ---------------------------------------------------------------------------
// Kernel 3: SCATTER copy, REVERSED block order. The last-read channels of x
// (still L2-resident from mean_kernel) are consumed first, before this
// kernel's write stream evicts them. Reads default-cached, stores streaming.
// ---------------------------------------------------------------------------
__global__ __launch_bounds__(256) void scatter_kernel(
    const float* __restrict__ x, float* __restrict__ out)
{
    const int b    = (NB * C - 1) - blockIdx.x;     // reverse order
    const int n    = b >> 8;
    const int slot = __ldg(&g_dst[b]);

    const float4* __restrict__ src =
        reinterpret_cast<const float4*>(x + (size_t)b * HW);   // linear read

    size_t dst_ch;
    if (slot < CH) dst_ch = (size_t)n * CH + slot;                          // selected
    else           dst_ch = (size_t)NB * CH + (size_t)n * CH + (slot - CH); // remaining
    float4* __restrict__ dst = reinterpret_cast<float4*>(out + dst_ch * HW);

    #pragma unroll
    for (int half = 0; half < 2; ++half) {
        const int base = half * (HW4 / 2) + threadIdx.x;
        float4 r[8];
        #pragma unroll
        for (int k = 0; k < 8; ++k)
            r[k] = src[base + k * 256];
        #pragma unroll
        for (int k = 0; k < 8; ++k)
            __stcs(&dst[base + k * 256], r[k]);
    }
}

// ---------------------------------------------------------------------------
extern "C" void kernel_launch(void* const* d_in, const int* in_sizes, int n_in,
                              void* d_out, int out_size)
{
    const float* x  = (const float*)d_in[0];
    const float* W1 = (const float*)d_in[1];
    const float* b1 = (const float*)d_in[2];
    const float* W2 = (const float*)d_in[3];
    const float* b2 = (const float*)d_in[4];
    float* out = (float*)d_out;

    mean_kernel<<<NB * C, 256>>>(x);
    mlp_rank_kernel<<<NB, 256>>>(W1, b1, W2, b2);
    scatter_kernel<<<NB * C, 256>>>(x, out);
}